// round 13
// baseline (speedup 1.0000x reference)
#include <cuda_runtime.h>
#include <cuda_fp16.h>
#include <math.h>
#include <stdint.h>

#define N_NODES 20000
#define N_EDGES 320000
#define KMIX    5
#define FIN     256
#define FOUT    128
#define KO      (KMIX*FOUT)   /* 640 */
#define MASKW   (FIN/32)      /* 8 */
#define NPB     8             /* nodes per block in prep_x */
#define PREPB   (N_NODES/NPB) /* 2500 prep blocks */
#define CNTB    ((N_EDGES + 255)/256) /* 1250 count blocks */

// ---------------- static device scratch (no allocs allowed) ----------------
static __device__ __align__(16) half     g_X0h[N_NODES*FIN];
static __device__ __align__(16) unsigned g_mask[N_NODES*MASKW];
static __device__ __align__(16) float    g_gamma[KMIX*N_NODES];
static __device__ __align__(16) float    g_invvar[KMIX*FIN];
static __device__ __align__(16) float    g_dinv[N_NODES];
static __device__ __align__(16) int      g_cnt[N_NODES];
static __device__ __align__(16) int      g_rowptr[N_NODES+1];
static __device__ __align__(16) int      g_wpos[N_NODES];
static __device__ __align__(16) int      g_ccol[N_EDGES];
static __device__ __align__(16) float    g_swn[N_NODES];
static __device__ int g_total;
// fp16 A matrices (SpMM outputs), row-major [N_NODES, 256]
static __device__ __align__(16) half     g_G1[N_NODES*FIN];
static __device__ __align__(16) half     g_G2[N_NODES*FIN];
static __device__ __align__(16) half     g_G3[N_NODES*FIN];
// fp16 transposed weights: [NCOLS rows x 256 K] K-major (= B^T)
static __device__ __align__(16) half     g_Wt [FOUT*FIN];
static __device__ __align__(16) half     g_Wmt[KO*FIN];
static __device__ __align__(16) half     g_Wct[KO*FIN];
// fp16 c1 = G1 @ W
static __device__ __align__(16) half     g_C1[N_NODES*FOUT];
static __device__ int g_is64;

// ================= helpers =================================================
__device__ __forceinline__ uint32_t smem_u32(const void* p) {
    uint32_t a;
    asm("{ .reg .u64 t; cvta.to.shared.u64 t, %1; cvt.u32.u64 %0, t; }" : "=r"(a) : "l"(p));
    return a;
}
#define SW128(o) ((o) ^ (((o) >> 3) & 0x70))

__device__ __forceinline__ void ldsm_x4(uint32_t* r, uint32_t addr) {
    asm volatile("ldmatrix.sync.aligned.m8n8.x4.shared.b16 {%0,%1,%2,%3}, [%4];"
                 : "=r"(r[0]), "=r"(r[1]), "=r"(r[2]), "=r"(r[3]) : "r"(addr));
}
__device__ __forceinline__ void mma_fp16(float* c, const uint32_t* a,
                                         uint32_t b0, uint32_t b1) {
    asm volatile(
        "mma.sync.aligned.m16n8k16.row.col.f32.f16.f16.f32 "
        "{%0,%1,%2,%3},{%4,%5,%6,%7},{%8,%9},{%0,%1,%2,%3};"
        : "+f"(c[0]), "+f"(c[1]), "+f"(c[2]), "+f"(c[3])
        : "r"(a[0]), "r"(a[1]), "r"(a[2]), "r"(a[3]), "r"(b0), "r"(b1));
}
__device__ __forceinline__ void cp_async16(uint32_t dst, const void* src, bool valid) {
    int sz = valid ? 16 : 0;
    asm volatile("cp.async.cg.shared.global [%0], [%1], 16, %2;"
                 :: "r"(dst), "l"(src), "r"(sz));
}
#define CP_COMMIT() asm volatile("cp.async.commit_group;" ::: "memory")
#define CP_WAIT2()  asm volatile("cp.async.wait_group 2;" ::: "memory")
#define CP_WAIT1()  asm volatile("cp.async.wait_group 1;" ::: "memory")
#define CP_WAIT0()  asm volatile("cp.async.wait_group 0;" ::: "memory")

__device__ __forceinline__ int load_row(const void* ei, int e) {
    if (g_is64) return (int)((const long long*)ei)[e];
    return ((const int*)ei)[e];
}
__device__ __forceinline__ int load_col(const void* ei, int e) {
    if (g_is64) return (int)((const long long*)ei)[N_EDGES + e];
    return ((const int*)ei)[N_EDGES + e];
}

// ---------------- merged setup: detect dtype + weights + cnt + zero out ----
__global__ void setup_all(const int* __restrict__ ei32,
                          const float* __restrict__ means,
                          const float* __restrict__ logvars,
                          const float* __restrict__ W,
                          float* __restrict__ out) {
    int idx = blockIdx.x * blockDim.x + threadIdx.x;
    if (idx == 0) {
        int is64 = 1;
        for (int i = 0; i < 128; i++)
            if (ei32[2*i + 1] != 0) { is64 = 0; break; }
        g_is64 = is64;
        g_total = 0;
    }
    if (idx < N_NODES) g_cnt[idx] = 0;
    if (idx < KMIX*FIN) g_invvar[idx] = expf(-logvars[idx]);
    if (idx < KO*FIN) {
        int j = idx / FIN, i = idx % FIN;               // j = k*FOUT+o
        int k = j / FOUT, o = j % FOUT;
        float w = W[i*FOUT + o];
        g_Wmt[idx] = __float2half_rn(means[k*FIN + i] * w);
        g_Wct[idx] = __float2half_rn(expf(logvars[k*FIN + i]) * w * w);
        if (j < FOUT) g_Wt[idx] = __float2half_rn(W[i*FOUT + j]);
    }
    if (idx < (N_NODES*FOUT)/4)
        ((float4*)out)[idx] = make_float4(0.f, 0.f, 0.f, 0.f);
}

// ---------------- fused prep_x + count_deg (role-split blocks) -------------
__global__ __launch_bounds__(FIN) void prep_and_count(const float* __restrict__ x,
                       const float* __restrict__ means,
                       const float* __restrict__ logp,
                       const void* __restrict__ ei) {
    if (blockIdx.x >= PREPB) {
        int e = (blockIdx.x - PREPB) * 256 + threadIdx.x;
        if (e < N_EDGES) atomicAdd(&g_cnt[load_row(ei, e)], 1);
        return;
    }
    int t = threadIdx.x;
    int lane = t & 31, w = t >> 5;
    int nbase = blockIdx.x * NPB;

    float mk[KMIX], iv[KMIX];
#pragma unroll
    for (int k = 0; k < KMIX; k++) {
        mk[k] = means[k*FIN + t];
        iv[k] = g_invvar[k*FIN + t];
    }

    __shared__ float red[NPB][8][KMIX];
    __shared__ float lpv[KMIX];
    if (t < KMIX) lpv[t] = logp[t];

#pragma unroll
    for (int nn = 0; nn < NPB; nn++) {
        int n = nbase + nn;
        float v = x[(size_t)n*FIN + t];
        bool isn = !(v == v);
        g_X0h[(size_t)n*FIN + t] = __float2half_rn(isn ? 0.f : v);
        unsigned bal = __ballot_sync(0xffffffffu, isn);
        if (lane == 0) g_mask[n*MASKW + w] = bal;

        float d[KMIX];
#pragma unroll
        for (int k = 0; k < KMIX; k++) {
            float diff = isn ? 0.f : (v - mk[k]);
            d[k] = diff * diff * iv[k];
        }
#pragma unroll
        for (int k = 0; k < KMIX; k++)
            for (int off = 16; off > 0; off >>= 1)
                d[k] += __shfl_down_sync(0xffffffffu, d[k], off);
        if (lane == 0)
            for (int k = 0; k < KMIX; k++) red[nn][w][k] = d[k];
    }
    __syncthreads();
    if (t < NPB) {
        int n = nbase + t;
        float s[KMIX], m = -1e30f;
#pragma unroll
        for (int k = 0; k < KMIX; k++) {
            float acc = 0.f;
            for (int ww = 0; ww < 8; ww++) acc += red[t][ww][k];
            s[k] = lpv[k] - 0.5f * acc;
            m = fmaxf(m, s[k]);
        }
        float ssum = 0.f, e[KMIX];
#pragma unroll
        for (int k = 0; k < KMIX; k++) { e[k] = expf(s[k] - m); ssum += e[k]; }
        float inv = 1.f / ssum;
#pragma unroll
        for (int k = 0; k < KMIX; k++) g_gamma[k*N_NODES + n] = e[k] * inv;
    }
}

// ---------------- CSR build ------------------------------------------------
__global__ __launch_bounds__(256) void compute_offsets() {
    __shared__ int wsums[8];
    __shared__ int blockbase;
    int i = blockIdx.x * 256 + threadIdx.x;
    int lane = threadIdx.x & 31, w = threadIdx.x >> 5;
    int v = (i < N_NODES) ? g_cnt[i] : 0;
    int xv = v;
#pragma unroll
    for (int off = 1; off < 32; off <<= 1) {
        int y = __shfl_up_sync(0xffffffffu, xv, off);
        if (lane >= off) xv += y;
    }
    if (lane == 31) wsums[w] = xv;
    __syncthreads();
    if (threadIdx.x == 0) {
        int s = 0;
#pragma unroll
        for (int j = 0; j < 8; j++) { int tv = wsums[j]; wsums[j] = s; s += tv; }
        blockbase = atomicAdd(&g_total, s);
    }
    __syncthreads();
    if (i < N_NODES) {
        int start = blockbase + wsums[w] + (xv - v);
        g_rowptr[i] = start;
        g_wpos[i]   = start;
        g_dinv[i]   = rsqrtf((float)(v + 1));
    }
}

// 4 edges per thread -> 4 independent atomic chains in flight
__global__ void scatter_edges(const void* __restrict__ ei) {
    int base = (blockIdx.x * blockDim.x + threadIdx.x) * 4;
#pragma unroll
    for (int q = 0; q < 4; q++) {
        int e = base + q;
        if (e < N_EDGES) {
            int r = load_row(ei, e);
            int c = load_col(ei, e);
            int p = atomicAdd(&g_wpos[r], 1);
            g_ccol[p] = c;
        }
    }
}

// ---------------- fused SpMM (fp16 gather, 8-edge unroll) ------------------
__global__ __launch_bounds__(128) void spmm_kernel() {
    int r = blockIdx.x;
    int t = threadIdx.x;               // 0..127
    int mw = t >> 4;
    int b0 = (2*t) & 31;
    float dr = g_dinv[r];
    int start = g_rowptr[r], end = start + g_cnt[r];
    float a1x=0.f, a1y=0.f, a2x=0.f, a2y=0.f, a3x=0.f, a3y=0.f, sw=0.f;
    const __half2* X = (const __half2*)g_X0h;

    int e = start;
    for (; e + 8 <= end; e += 8) {
        int   c[8]; float d[8]; float2 xv[8]; unsigned m[8];
#pragma unroll
        for (int q = 0; q < 8; q++) c[q] = g_ccol[e + q];
#pragma unroll
        for (int q = 0; q < 8; q++) d[q] = g_dinv[c[q]];
#pragma unroll
        for (int q = 0; q < 8; q++) xv[q] = __half22float2(X[c[q]*(FIN/2) + t]);
#pragma unroll
        for (int q = 0; q < 8; q++) m[q] = g_mask[c[q]*MASKW + mw] >> b0;
#pragma unroll
        for (int q = 0; q < 8; q++) {
            a1x += d[q]*xv[q].x; a1y += d[q]*xv[q].y;
            if (m[q] & 1u) { a2x += d[q]; a3x += d[q]*d[q]; }
            if (m[q] & 2u) { a2y += d[q]; a3y += d[q]*d[q]; }
            sw += d[q];
        }
    }
    for (; e < end; e++) {
        int c0 = g_ccol[e];
        float d0 = g_dinv[c0];
        float2 x0 = __half22float2(X[c0*(FIN/2) + t]);
        unsigned m0 = g_mask[c0*MASKW + mw] >> b0;
        a1x += d0*x0.x; a1y += d0*x0.y;
        if (m0 & 1u) { a2x += d0; a3x += d0*d0; }
        if (m0 & 2u) { a2y += d0; a3y += d0*d0; }
        sw += d0;
    }
    {   // self loop
        float2 xr = __half22float2(X[r*(FIN/2) + t]);
        unsigned mr = g_mask[r*MASKW + mw] >> b0;
        a1x += dr*xr.x; a1y += dr*xr.y;
        if (mr & 1u) { a2x += dr; a3x += dr*dr; }
        if (mr & 2u) { a2y += dr; a3y += dr*dr; }
        sw += dr;
    }
    size_t o = (size_t)r*(FIN/2) + t;
    float dr2 = dr * dr;
    ((__half2*)g_G1)[o] = __floats2half2_rn(dr * a1x,  dr * a1y);
    ((__half2*)g_G2)[o] = __floats2half2_rn(dr * a2x,  dr * a2y);
    ((__half2*)g_G3)[o] = __floats2half2_rn(dr2 * a3x, dr2 * a3y);
    if (t == 0) g_swn[r] = dr * sw;
}

// ---------------- fused GEMMs (fp16, 3-stage cp.async pipeline) ------------
// CTA tile 128 rows x 64 cols; 8 warps (4M x 2N), warp tile 32x32.
#define STA 0
#define STB 16384
#define STG_SZ 24576
#define SMEM_T (3*STG_SZ)   /* 72 KB, 2 CTAs/SM */

__device__ __forceinline__ float ex_relu(float mu, float sig) {
    if (sig <= 0.f) return fmaxf(mu, 0.f);
    float ss = sqrtf(sig);
    float w = mu / ss;
    return ss * (expf(-0.5f * w * w) * 0.3989422804014327f
                 + 0.5f * w * (1.f + erff(w * 0.7071067811865476f)));
}

__device__ __forceinline__ void pipe_wait(int ch, int nch) {
    if (ch + 3 <= nch)      { CP_WAIT2(); }
    else if (ch + 2 <= nch) { CP_WAIT1(); }
    else                    { CP_WAIT0(); }
}

__device__ __forceinline__ void compute_chunk(uint32_t base, uint32_t aRowOff,
                                              uint32_t bRowOff, uint32_t lhc,
                                              uint32_t swz, float (&acc)[2][4][4]) {
#pragma unroll
    for (int ks = 0; ks < 4; ks++) {
        uint32_t xoff = ((uint32_t)ks * 32 + lhc) ^ swz;
        uint32_t a[2][4], b[2][4];
        ldsm_x4(a[0], base + STA + aRowOff + xoff);
        ldsm_x4(a[1], base + STA + aRowOff + 16*128 + xoff);
        ldsm_x4(b[0], base + STB + bRowOff + xoff);
        ldsm_x4(b[1], base + STB + bRowOff + 16*128 + xoff);
#pragma unroll
        for (int mf = 0; mf < 2; mf++)
#pragma unroll
            for (int nf = 0; nf < 2; nf++) {
                mma_fp16(acc[mf][2*nf],   a[mf], b[nf][0], b[nf][2]);
                mma_fp16(acc[mf][2*nf+1], a[mf], b[nf][1], b[nf][3]);
            }
    }
}

// ---- phase 0: c1 = G1 @ W -> g_C1 (fp16), grid (157, 2) ----
__global__ __launch_bounds__(256, 2) void gemm_c1() {
    const int tile = blockIdx.x, nh = blockIdx.y;
    extern __shared__ __align__(1024) char smem[];
    uint32_t smb = smem_u32(smem);
    int tid = threadIdx.x;
    int wid = tid >> 5, lane = tid & 31;
    int wm = wid >> 1, wn = wid & 1;
    int lrow = lane & 15;
    uint32_t lhc = (uint32_t)(lane >> 4) * 16;
    uint32_t swz = (uint32_t)(lrow & 7) << 4;
    uint32_t aRowOff = (uint32_t)(wm * 32 + lrow) * 128;
    uint32_t bRowOff = (uint32_t)(wn * 32 + lrow) * 128;

    float acc[2][4][4];
#pragma unroll
    for (int i = 0; i < 2; i++)
#pragma unroll
        for (int j = 0; j < 4; j++)
#pragma unroll
            for (int q = 0; q < 4; q++) acc[i][j][q] = 0.f;

    auto load_stage = [&](int kc, int buf) {
        uint32_t base = smb + buf * STG_SZ;
#pragma unroll
        for (int it = 0; it < 4; it++) {
            int idx = it * 256 + tid;
            int row = idx >> 3, kq = idx & 7;
            uint32_t so = SW128((uint32_t)row * 128 + (uint32_t)kq * 16);
            int grow = tile * 128 + row;
            bool av = grow < N_NODES;
            size_t go = (size_t)(av ? grow : 0) * FIN + kc * 64 + kq * 8;
            cp_async16(base + STA + so, g_G1 + go, av);
        }
#pragma unroll
        for (int it = 0; it < 2; it++) {
            int idx = it * 256 + tid;
            int row = idx >> 3, kq = idx & 7;
            uint32_t so = SW128((uint32_t)row * 128 + (uint32_t)kq * 16);
            size_t bo = (size_t)(nh * 64 + row) * FIN + kc * 64 + kq * 8;
            cp_async16(base + STB + so, g_Wt + bo, true);
        }
        CP_COMMIT();
    };

    load_stage(0, 0);
    load_stage(1, 1);
    load_stage(2, 2);
    for (int ch = 0; ch < 4; ch++) {
        pipe_wait(ch, 4);
        __syncthreads();
        compute_chunk(smb + (ch % 3) * STG_SZ, aRowOff, bRowOff, lhc, swz, acc);
        __syncthreads();
        if (ch + 3 < 4) load_stage(ch + 3, (ch + 3) % 3);
    }

    int cb = nh * 64 + wn * 32 + (lane & 3) * 2;
#pragma unroll
    for (int mf = 0; mf < 2; mf++) {
        int r0 = tile * 128 + wm * 32 + mf * 16 + (lane >> 2);
#pragma unroll
        for (int n8 = 0; n8 < 4; n8++) {
            int c = cb + n8 * 8;
            if (r0 < N_NODES)
                *(__half2*)(g_C1 + (size_t)r0 * FOUT + c) =
                    __floats2half2_rn(acc[mf][n8][0], acc[mf][n8][1]);
            if (r0 + 8 < N_NODES)
                *(__half2*)(g_C1 + (size_t)(r0 + 8) * FOUT + c) =
                    __floats2half2_rn(acc[mf][n8][2], acc[mf][n8][3]);
        }
    }
}

// ---- phase 1: mx/cv GEMMs + fused ExRelu epilogue, grid (157, 2, 5) ----
__global__ __launch_bounds__(256, 2) void gemm_mix(const float* __restrict__ bias,
                                                   float* __restrict__ out) {
    const int tile = blockIdx.x, nh = blockIdx.y, kk = blockIdx.z;

    extern __shared__ __align__(1024) char smem[];
    uint32_t smb = smem_u32(smem);
    int tid = threadIdx.x;
    int wid = tid >> 5, lane = tid & 31;
    int wm = wid >> 1, wn = wid & 1;
    int lrow = lane & 15;
    uint32_t lhc = (uint32_t)(lane >> 4) * 16;
    uint32_t swz = (uint32_t)(lrow & 7) << 4;
    uint32_t aRowOff = (uint32_t)(wm * 32 + lrow) * 128;
    uint32_t bRowOff = (uint32_t)(wn * 32 + lrow) * 128;

    float mxr[2][4][4], acc[2][4][4];
#pragma unroll
    for (int i = 0; i < 2; i++)
#pragma unroll
        for (int j = 0; j < 4; j++)
#pragma unroll
            for (int q = 0; q < 4; q++) { mxr[i][j][q] = 0.f; acc[i][j][q] = 0.f; }

    auto load_stage = [&](int ch, int buf) {
        int phase = ch >> 2;
        int kc = ch & 3;
        const half* __restrict__ A = phase ? g_G3 : g_G2;
        const half* __restrict__ B = phase ? g_Wct : g_Wmt;
        int jb0 = kk * FOUT + nh * 64;
        uint32_t base = smb + buf * STG_SZ;
#pragma unroll
        for (int it = 0; it < 4; it++) {
            int idx = it * 256 + tid;
            int row = idx >> 3, kq = idx & 7;
            uint32_t so = SW128((uint32_t)row * 128 + (uint32_t)kq * 16);
            int grow = tile * 128 + row;
            bool av = grow < N_NODES;
            size_t go = (size_t)(av ? grow : 0) * FIN + kc * 64 + kq * 8;
            cp_async16(base + STA + so, A + go, av);
        }
#pragma unroll
        for (int it = 0; it < 2; it++) {
            int idx = it * 256 + tid;
            int row = idx >> 3, kq = idx & 7;
            uint32_t so = SW128((uint32_t)row * 128 + (uint32_t)kq * 16);
            size_t bo = (size_t)(jb0 + row) * FIN + kc * 64 + kq * 8;
            cp_async16(base + STB + so, B + bo, true);
        }
        CP_COMMIT();
    };

    load_stage(0, 0);
    load_stage(1, 1);
    load_stage(2, 2);
    for (int ch = 0; ch < 8; ch++) {
        pipe_wait(ch, 8);
        __syncthreads();
        uint32_t base = smb + (ch % 3) * STG_SZ;
        if (ch < 4)
            compute_chunk(base, aRowOff, bRowOff, lhc, swz, mxr);
        else
            compute_chunk(base, aRowOff, bRowOff, lhc, swz, acc);
        __syncthreads();
        if (ch + 3 < 8) load_stage(ch + 3, (ch + 3) % 3);
    }

    // epilogue: out += gamma_k * exrelu(c1 + mx + swn*bias, cv)
    int cb = nh * 64 + wn * 32 + (lane & 3) * 2;
#pragma unroll
    for (int mf = 0; mf < 2; mf++) {
#pragma unroll
        for (int rh = 0; rh < 2; rh++) {
            int r = tile * 128 + wm * 32 + mf * 16 + (lane >> 2) + rh * 8;
            if (r >= N_NODES) continue;
            float ga = g_gamma[kk * N_NODES + r];
            float swr = g_swn[r];
#pragma unroll
            for (int n8 = 0; n8 < 4; n8++) {
                int c = cb + n8 * 8;
                float2 c1v = __half22float2(*(const __half2*)(g_C1 + (size_t)r * FOUT + c));
                float2 bv  = *(const float2*)(bias + c);
                float mu0 = c1v.x + mxr[mf][n8][2*rh]   + swr * bv.x;
                float mu1 = c1v.y + mxr[mf][n8][2*rh+1] + swr * bv.y;
                float t0 = ga * ex_relu(mu0, acc[mf][n8][2*rh]);
                float t1 = ga * ex_relu(mu1, acc[mf][n8][2*rh+1]);
                atomicAdd(out + (size_t)r * FOUT + c,     t0);
                atomicAdd(out + (size_t)r * FOUT + c + 1, t1);
            }
        }
    }
}

// ---------------- launch ---------------------------------------------------
extern "C" void kernel_launch(void* const* d_in, const int* in_sizes, int n_in,
                              void* d_out, int out_size) {
    const float* x       = (const float*)d_in[0];
    const void*  ei      = d_in[1];
    const float* logp    = (const float*)d_in[2];
    const float* means   = (const float*)d_in[3];
    const float* logvars = (const float*)d_in[4];
    const float* weight  = (const float*)d_in[5];
    const float* bias    = (const float*)d_in[6];
    float*       out     = (float*)d_out;

    cudaFuncSetAttribute(gemm_c1,  cudaFuncAttributeMaxDynamicSharedMemorySize, SMEM_T);
    cudaFuncSetAttribute(gemm_mix, cudaFuncAttributeMaxDynamicSharedMemorySize, SMEM_T);

    setup_all<<<(N_NODES*FOUT/4 + 255)/256, 256>>>((const int*)ei, means, logvars,
                                                   weight, out);
    prep_and_count<<<PREPB + CNTB, FIN>>>(x, means, logp, ei);
    compute_offsets<<<(N_NODES + 255)/256, 256>>>();
    scatter_edges<<<(N_EDGES/4 + 255)/256, 256>>>(ei);
    spmm_kernel<<<N_NODES, 128>>>();

    const int MT = (N_NODES + 127) / 128;   // 157
    gemm_c1 <<<dim3(MT, 2), 256, SMEM_T>>>();
    gemm_mix<<<dim3(MT, 2, KMIX), 256, SMEM_T>>>(bias, out);
}

// round 14
// speedup vs baseline: 1.5429x; 1.5429x over previous
#include <cuda_runtime.h>
#include <cuda_fp16.h>
#include <math.h>
#include <stdint.h>

#define N_NODES 20000
#define N_EDGES 320000
#define KMIX    5
#define FIN     256
#define FOUT    128
#define KO      (KMIX*FOUT)   /* 640 */
#define MASKW   (FIN/32)      /* 8 */
#define NPB     8             /* nodes per block in prep_x */
#define PREPB   (N_NODES/NPB) /* 2500 prep blocks */
#define CNTB    ((N_EDGES + 255)/256) /* 1250 count blocks */

// ---------------- static device scratch (no allocs allowed) ----------------
static __device__ __align__(16) half     g_X0h[N_NODES*FIN];
static __device__ __align__(16) unsigned g_mask[N_NODES*MASKW];
static __device__ __align__(16) float    g_gamma[KMIX*N_NODES];
static __device__ __align__(16) float    g_invvar[KMIX*FIN];
static __device__ __align__(16) float    g_dinv[N_NODES];
static __device__ __align__(16) int      g_cnt[N_NODES];
static __device__ __align__(16) int      g_rowptr[N_NODES+1];
static __device__ __align__(16) int      g_wpos[N_NODES];
static __device__ __align__(16) int      g_ccol[N_EDGES];
static __device__ __align__(16) float    g_swn[N_NODES];
static __device__ int g_total;
// fp16 A matrices (SpMM outputs), row-major [N_NODES, 256]
static __device__ __align__(16) half     g_G1[N_NODES*FIN];
static __device__ __align__(16) half     g_G2[N_NODES*FIN];
static __device__ __align__(16) half     g_G3[N_NODES*FIN];
// fp16 transposed weights: [NCOLS rows x 256 K] K-major (= B^T)
static __device__ __align__(16) half     g_Wt [FOUT*FIN];
static __device__ __align__(16) half     g_Wmt[KO*FIN];
static __device__ __align__(16) half     g_Wct[KO*FIN];
// fp16 c1 = G1 @ W
static __device__ __align__(16) half     g_C1[N_NODES*FOUT];
static __device__ int g_is64;

// ================= helpers =================================================
__device__ __forceinline__ uint32_t smem_u32(const void* p) {
    uint32_t a;
    asm("{ .reg .u64 t; cvta.to.shared.u64 t, %1; cvt.u32.u64 %0, t; }" : "=r"(a) : "l"(p));
    return a;
}
#define SW128(o) ((o) ^ (((o) >> 3) & 0x70))

__device__ __forceinline__ void ldsm_x4(uint32_t* r, uint32_t addr) {
    asm volatile("ldmatrix.sync.aligned.m8n8.x4.shared.b16 {%0,%1,%2,%3}, [%4];"
                 : "=r"(r[0]), "=r"(r[1]), "=r"(r[2]), "=r"(r[3]) : "r"(addr));
}
__device__ __forceinline__ void mma_fp16(float* c, const uint32_t* a,
                                         uint32_t b0, uint32_t b1) {
    asm volatile(
        "mma.sync.aligned.m16n8k16.row.col.f32.f16.f16.f32 "
        "{%0,%1,%2,%3},{%4,%5,%6,%7},{%8,%9},{%0,%1,%2,%3};"
        : "+f"(c[0]), "+f"(c[1]), "+f"(c[2]), "+f"(c[3])
        : "r"(a[0]), "r"(a[1]), "r"(a[2]), "r"(a[3]), "r"(b0), "r"(b1));
}
__device__ __forceinline__ void cp_async16(uint32_t dst, const void* src, bool valid) {
    int sz = valid ? 16 : 0;
    asm volatile("cp.async.cg.shared.global [%0], [%1], 16, %2;"
                 :: "r"(dst), "l"(src), "r"(sz));
}
#define CP_COMMIT() asm volatile("cp.async.commit_group;" ::: "memory")
#define CP_WAIT1()  asm volatile("cp.async.wait_group 1;" ::: "memory")
#define CP_WAIT0()  asm volatile("cp.async.wait_group 0;" ::: "memory")

__device__ __forceinline__ int load_row(const void* ei, int e) {
    if (g_is64) return (int)((const long long*)ei)[e];
    return ((const int*)ei)[e];
}
__device__ __forceinline__ int load_col(const void* ei, int e) {
    if (g_is64) return (int)((const long long*)ei)[N_EDGES + e];
    return ((const int*)ei)[N_EDGES + e];
}

// ---------------- merged setup: detect dtype + weights + cnt + zero out ----
__global__ void setup_all(const int* __restrict__ ei32,
                          const float* __restrict__ means,
                          const float* __restrict__ logvars,
                          const float* __restrict__ W,
                          float* __restrict__ out) {
    int idx = blockIdx.x * blockDim.x + threadIdx.x;
    if (idx == 0) {
        int is64 = 1;
        for (int i = 0; i < 128; i++)
            if (ei32[2*i + 1] != 0) { is64 = 0; break; }
        g_is64 = is64;
        g_total = 0;
    }
    if (idx < N_NODES) g_cnt[idx] = 0;
    if (idx < KMIX*FIN) g_invvar[idx] = expf(-logvars[idx]);
    if (idx < KO*FIN) {
        int j = idx / FIN, i = idx % FIN;               // j = k*FOUT+o
        int k = j / FOUT, o = j % FOUT;
        float w = W[i*FOUT + o];
        g_Wmt[idx] = __float2half_rn(means[k*FIN + i] * w);
        g_Wct[idx] = __float2half_rn(expf(logvars[k*FIN + i]) * w * w);
        if (j < FOUT) g_Wt[idx] = __float2half_rn(W[i*FOUT + j]);
    }
    if (idx < (N_NODES*FOUT)/4)
        ((float4*)out)[idx] = make_float4(0.f, 0.f, 0.f, 0.f);
}

// ---------------- fused prep_x + count_deg (role-split blocks) -------------
__global__ __launch_bounds__(FIN) void prep_and_count(const float* __restrict__ x,
                       const float* __restrict__ means,
                       const float* __restrict__ logp,
                       const void* __restrict__ ei) {
    if (blockIdx.x >= PREPB) {
        int e = (blockIdx.x - PREPB) * 256 + threadIdx.x;
        if (e < N_EDGES) atomicAdd(&g_cnt[load_row(ei, e)], 1);
        return;
    }
    int t = threadIdx.x;
    int lane = t & 31, w = t >> 5;
    int nbase = blockIdx.x * NPB;

    float mk[KMIX], iv[KMIX];
#pragma unroll
    for (int k = 0; k < KMIX; k++) {
        mk[k] = means[k*FIN + t];
        iv[k] = g_invvar[k*FIN + t];
    }

    __shared__ float red[NPB][8][KMIX];
    __shared__ float lpv[KMIX];
    if (t < KMIX) lpv[t] = logp[t];

#pragma unroll
    for (int nn = 0; nn < NPB; nn++) {
        int n = nbase + nn;
        float v = x[(size_t)n*FIN + t];
        bool isn = !(v == v);
        g_X0h[(size_t)n*FIN + t] = __float2half_rn(isn ? 0.f : v);
        unsigned bal = __ballot_sync(0xffffffffu, isn);
        if (lane == 0) g_mask[n*MASKW + w] = bal;

        float d[KMIX];
#pragma unroll
        for (int k = 0; k < KMIX; k++) {
            float diff = isn ? 0.f : (v - mk[k]);
            d[k] = diff * diff * iv[k];
        }
#pragma unroll
        for (int k = 0; k < KMIX; k++)
            for (int off = 16; off > 0; off >>= 1)
                d[k] += __shfl_down_sync(0xffffffffu, d[k], off);
        if (lane == 0)
            for (int k = 0; k < KMIX; k++) red[nn][w][k] = d[k];
    }
    __syncthreads();
    if (t < NPB) {
        int n = nbase + t;
        float s[KMIX], m = -1e30f;
#pragma unroll
        for (int k = 0; k < KMIX; k++) {
            float acc = 0.f;
            for (int ww = 0; ww < 8; ww++) acc += red[t][ww][k];
            s[k] = lpv[k] - 0.5f * acc;
            m = fmaxf(m, s[k]);
        }
        float ssum = 0.f, e[KMIX];
#pragma unroll
        for (int k = 0; k < KMIX; k++) { e[k] = expf(s[k] - m); ssum += e[k]; }
        float inv = 1.f / ssum;
#pragma unroll
        for (int k = 0; k < KMIX; k++) g_gamma[k*N_NODES + n] = e[k] * inv;
    }
}

// ---------------- CSR build ------------------------------------------------
__global__ __launch_bounds__(256) void compute_offsets() {
    __shared__ int wsums[8];
    __shared__ int blockbase;
    int i = blockIdx.x * 256 + threadIdx.x;
    int lane = threadIdx.x & 31, w = threadIdx.x >> 5;
    int v = (i < N_NODES) ? g_cnt[i] : 0;
    int xv = v;
#pragma unroll
    for (int off = 1; off < 32; off <<= 1) {
        int y = __shfl_up_sync(0xffffffffu, xv, off);
        if (lane >= off) xv += y;
    }
    if (lane == 31) wsums[w] = xv;
    __syncthreads();
    if (threadIdx.x == 0) {
        int s = 0;
#pragma unroll
        for (int j = 0; j < 8; j++) { int tv = wsums[j]; wsums[j] = s; s += tv; }
        blockbase = atomicAdd(&g_total, s);
    }
    __syncthreads();
    if (i < N_NODES) {
        int start = blockbase + wsums[w] + (xv - v);
        g_rowptr[i] = start;
        g_wpos[i]   = start;
        g_dinv[i]   = rsqrtf((float)(v + 1));
    }
}

__global__ void scatter_edges(const void* __restrict__ ei) {
    int e = blockIdx.x * blockDim.x + threadIdx.x;
    if (e < N_EDGES) {
        int r = load_row(ei, e);
        int c = load_col(ei, e);
        int p = atomicAdd(&g_wpos[r], 1);
        g_ccol[p] = c;
    }
}

// ---------------- fused SpMM (fp16 gather, 8-edge unroll) ------------------
__global__ __launch_bounds__(128) void spmm_kernel() {
    int r = blockIdx.x;
    int t = threadIdx.x;               // 0..127
    int mw = t >> 4;
    int b0 = (2*t) & 31;
    float dr = g_dinv[r];
    int start = g_rowptr[r], end = start + g_cnt[r];
    float a1x=0.f, a1y=0.f, a2x=0.f, a2y=0.f, a3x=0.f, a3y=0.f, sw=0.f;
    const __half2* X = (const __half2*)g_X0h;

    int e = start;
    for (; e + 8 <= end; e += 8) {
        int   c[8]; float d[8]; float2 xv[8]; unsigned m[8];
#pragma unroll
        for (int q = 0; q < 8; q++) c[q] = g_ccol[e + q];
#pragma unroll
        for (int q = 0; q < 8; q++) d[q] = g_dinv[c[q]];
#pragma unroll
        for (int q = 0; q < 8; q++) xv[q] = __half22float2(X[c[q]*(FIN/2) + t]);
#pragma unroll
        for (int q = 0; q < 8; q++) m[q] = g_mask[c[q]*MASKW + mw] >> b0;
#pragma unroll
        for (int q = 0; q < 8; q++) {
            a1x += d[q]*xv[q].x; a1y += d[q]*xv[q].y;
            if (m[q] & 1u) { a2x += d[q]; a3x += d[q]*d[q]; }
            if (m[q] & 2u) { a2y += d[q]; a3y += d[q]*d[q]; }
            sw += d[q];
        }
    }
    for (; e < end; e++) {
        int c0 = g_ccol[e];
        float d0 = g_dinv[c0];
        float2 x0 = __half22float2(X[c0*(FIN/2) + t]);
        unsigned m0 = g_mask[c0*MASKW + mw] >> b0;
        a1x += d0*x0.x; a1y += d0*x0.y;
        if (m0 & 1u) { a2x += d0; a3x += d0*d0; }
        if (m0 & 2u) { a2y += d0; a3y += d0*d0; }
        sw += d0;
    }
    {   // self loop
        float2 xr = __half22float2(X[r*(FIN/2) + t]);
        unsigned mr = g_mask[r*MASKW + mw] >> b0;
        a1x += dr*xr.x; a1y += dr*xr.y;
        if (mr & 1u) { a2x += dr; a3x += dr*dr; }
        if (mr & 2u) { a2y += dr; a3y += dr*dr; }
        sw += dr;
    }
    size_t o = (size_t)r*(FIN/2) + t;
    float dr2 = dr * dr;
    ((__half2*)g_G1)[o] = __floats2half2_rn(dr * a1x,  dr * a1y);
    ((__half2*)g_G2)[o] = __floats2half2_rn(dr * a2x,  dr * a2y);
    ((__half2*)g_G3)[o] = __floats2half2_rn(dr2 * a3x, dr2 * a3y);
    if (t == 0) g_swn[r] = dr * sw;
}

// ---------------- fused GEMMs (fp16 single pass, R10/R12 core) -------------
// CTA tile 128 rows x 64 cols; 8 warps (4M x 2N), warp tile 32x32.
#define STA 0
#define STB 16384
#define STG_SZ 24576
#define SMEM_T (2*STG_SZ)   /* 48 KB */

__device__ __forceinline__ float ex_relu(float mu, float sig) {
    if (sig <= 0.f) return fmaxf(mu, 0.f);
    float ss = sqrtf(sig);
    float w = mu / ss;
    return ss * (expf(-0.5f * w * w) * 0.3989422804014327f
                 + 0.5f * w * (1.f + erff(w * 0.7071067811865476f)));
}

__device__ __forceinline__ void compute_chunk(uint32_t base, uint32_t aRowOff,
                                              uint32_t bRowOff, uint32_t lhc,
                                              uint32_t swz, float (&acc)[2][4][4]) {
#pragma unroll
    for (int ks = 0; ks < 4; ks++) {
        uint32_t xoff = ((uint32_t)ks * 32 + lhc) ^ swz;
        uint32_t a[2][4], b[2][4];
        ldsm_x4(a[0], base + STA + aRowOff + xoff);
        ldsm_x4(a[1], base + STA + aRowOff + 16*128 + xoff);
        ldsm_x4(b[0], base + STB + bRowOff + xoff);
        ldsm_x4(b[1], base + STB + bRowOff + 16*128 + xoff);
#pragma unroll
        for (int mf = 0; mf < 2; mf++)
#pragma unroll
            for (int nf = 0; nf < 2; nf++) {
                mma_fp16(acc[mf][2*nf],   a[mf], b[nf][0], b[nf][2]);
                mma_fp16(acc[mf][2*nf+1], a[mf], b[nf][1], b[nf][3]);
            }
    }
}

// ---- phase 0: c1 = G1 @ W -> g_C1 (fp16), grid (157, 2) ----
__global__ __launch_bounds__(256, 2) void gemm_c1() {
    const int tile = blockIdx.x, nh = blockIdx.y;
    extern __shared__ __align__(1024) char smem[];
    uint32_t smb = smem_u32(smem);
    int tid = threadIdx.x;
    int wid = tid >> 5, lane = tid & 31;
    int wm = wid >> 1, wn = wid & 1;
    int lrow = lane & 15;
    uint32_t lhc = (uint32_t)(lane >> 4) * 16;
    uint32_t swz = (uint32_t)(lrow & 7) << 4;
    uint32_t aRowOff = (uint32_t)(wm * 32 + lrow) * 128;
    uint32_t bRowOff = (uint32_t)(wn * 32 + lrow) * 128;

    float acc[2][4][4];
#pragma unroll
    for (int i = 0; i < 2; i++)
#pragma unroll
        for (int j = 0; j < 4; j++)
#pragma unroll
            for (int q = 0; q < 4; q++) acc[i][j][q] = 0.f;

    auto load_stage = [&](int kc, int buf) {
        uint32_t base = smb + buf * STG_SZ;
#pragma unroll
        for (int it = 0; it < 4; it++) {
            int idx = it * 256 + tid;
            int row = idx >> 3, kq = idx & 7;
            uint32_t so = SW128((uint32_t)row * 128 + (uint32_t)kq * 16);
            int grow = tile * 128 + row;
            bool av = grow < N_NODES;
            size_t go = (size_t)(av ? grow : 0) * FIN + kc * 64 + kq * 8;
            cp_async16(base + STA + so, g_G1 + go, av);
        }
#pragma unroll
        for (int it = 0; it < 2; it++) {
            int idx = it * 256 + tid;
            int row = idx >> 3, kq = idx & 7;
            uint32_t so = SW128((uint32_t)row * 128 + (uint32_t)kq * 16);
            size_t bo = (size_t)(nh * 64 + row) * FIN + kc * 64 + kq * 8;
            cp_async16(base + STB + so, g_Wt + bo, true);
        }
        CP_COMMIT();
    };

    load_stage(0, 0);
    load_stage(1, 1);
    for (int ch = 0; ch < 4; ch++) {
        if (ch < 3) { CP_WAIT1(); } else { CP_WAIT0(); }
        __syncthreads();
        compute_chunk(smb + (ch & 1) * STG_SZ, aRowOff, bRowOff, lhc, swz, acc);
        __syncthreads();
        if (ch + 2 < 4) load_stage(ch + 2, ch & 1);
    }

    int cb = nh * 64 + wn * 32 + (lane & 3) * 2;
#pragma unroll
    for (int mf = 0; mf < 2; mf++) {
        int r0 = tile * 128 + wm * 32 + mf * 16 + (lane >> 2);
#pragma unroll
        for (int n8 = 0; n8 < 4; n8++) {
            int c = cb + n8 * 8;
            if (r0 < N_NODES)
                *(__half2*)(g_C1 + (size_t)r0 * FOUT + c) =
                    __floats2half2_rn(acc[mf][n8][0], acc[mf][n8][1]);
            if (r0 + 8 < N_NODES)
                *(__half2*)(g_C1 + (size_t)(r0 + 8) * FOUT + c) =
                    __floats2half2_rn(acc[mf][n8][2], acc[mf][n8][3]);
        }
    }
}

// ---- phase 1: mx/cv GEMMs + fused ExRelu epilogue, grid (157, 2, 5) ----
__global__ __launch_bounds__(256, 2) void gemm_mix(const float* __restrict__ bias,
                                                   float* __restrict__ out) {
    const int tile = blockIdx.x, nh = blockIdx.y, kk = blockIdx.z;

    extern __shared__ __align__(1024) char smem[];
    uint32_t smb = smem_u32(smem);
    int tid = threadIdx.x;
    int wid = tid >> 5, lane = tid & 31;
    int wm = wid >> 1, wn = wid & 1;
    int lrow = lane & 15;
    uint32_t lhc = (uint32_t)(lane >> 4) * 16;
    uint32_t swz = (uint32_t)(lrow & 7) << 4;
    uint32_t aRowOff = (uint32_t)(wm * 32 + lrow) * 128;
    uint32_t bRowOff = (uint32_t)(wn * 32 + lrow) * 128;

    float mxr[2][4][4], acc[2][4][4];
#pragma unroll
    for (int i = 0; i < 2; i++)
#pragma unroll
        for (int j = 0; j < 4; j++)
#pragma unroll
            for (int q = 0; q < 4; q++) { mxr[i][j][q] = 0.f; acc[i][j][q] = 0.f; }

    auto load_stage = [&](int ch, int buf) {
        int phase = ch >> 2;
        int kc = ch & 3;
        const half* __restrict__ A = phase ? g_G3 : g_G2;
        const half* __restrict__ B = phase ? g_Wct : g_Wmt;
        int jb0 = kk * FOUT + nh * 64;
        uint32_t base = smb + buf * STG_SZ;
#pragma unroll
        for (int it = 0; it < 4; it++) {
            int idx = it * 256 + tid;
            int row = idx >> 3, kq = idx & 7;
            uint32_t so = SW128((uint32_t)row * 128 + (uint32_t)kq * 16);
            int grow = tile * 128 + row;
            bool av = grow < N_NODES;
            size_t go = (size_t)(av ? grow : 0) * FIN + kc * 64 + kq * 8;
            cp_async16(base + STA + so, A + go, av);
        }
#pragma unroll
        for (int it = 0; it < 2; it++) {
            int idx = it * 256 + tid;
            int row = idx >> 3, kq = idx & 7;
            uint32_t so = SW128((uint32_t)row * 128 + (uint32_t)kq * 16);
            size_t bo = (size_t)(jb0 + row) * FIN + kc * 64 + kq * 8;
            cp_async16(base + STB + so, B + bo, true);
        }
        CP_COMMIT();
    };

    load_stage(0, 0);
    load_stage(1, 1);
    for (int ch = 0; ch < 8; ch++) {
        if (ch < 7) { CP_WAIT1(); } else { CP_WAIT0(); }
        __syncthreads();
        uint32_t base = smb + (ch & 1) * STG_SZ;
        if (ch < 4)
            compute_chunk(base, aRowOff, bRowOff, lhc, swz, mxr);
        else
            compute_chunk(base, aRowOff, bRowOff, lhc, swz, acc);
        __syncthreads();
        if (ch + 2 < 8) load_stage(ch + 2, ch & 1);
    }

    // epilogue: out += gamma_k * exrelu(c1 + mx + swn*bias, cv)
    int cb = nh * 64 + wn * 32 + (lane & 3) * 2;
#pragma unroll
    for (int mf = 0; mf < 2; mf++) {
#pragma unroll
        for (int rh = 0; rh < 2; rh++) {
            int r = tile * 128 + wm * 32 + mf * 16 + (lane >> 2) + rh * 8;
            if (r >= N_NODES) continue;
            float ga = g_gamma[kk * N_NODES + r];
            float swr = g_swn[r];
#pragma unroll
            for (int n8 = 0; n8 < 4; n8++) {
                int c = cb + n8 * 8;
                float2 c1v = __half22float2(*(const __half2*)(g_C1 + (size_t)r * FOUT + c));
                float2 bv  = *(const float2*)(bias + c);
                float mu0 = c1v.x + mxr[mf][n8][2*rh]   + swr * bv.x;
                float mu1 = c1v.y + mxr[mf][n8][2*rh+1] + swr * bv.y;
                float t0 = ga * ex_relu(mu0, acc[mf][n8][2*rh]);
                float t1 = ga * ex_relu(mu1, acc[mf][n8][2*rh+1]);
                atomicAdd(out + (size_t)r * FOUT + c,     t0);
                atomicAdd(out + (size_t)r * FOUT + c + 1, t1);
            }
        }
    }
}

// ---------------- launch ---------------------------------------------------
extern "C" void kernel_launch(void* const* d_in, const int* in_sizes, int n_in,
                              void* d_out, int out_size) {
    const float* x       = (const float*)d_in[0];
    const void*  ei      = d_in[1];
    const float* logp    = (const float*)d_in[2];
    const float* means   = (const float*)d_in[3];
    const float* logvars = (const float*)d_in[4];
    const float* weight  = (const float*)d_in[5];
    const float* bias    = (const float*)d_in[6];
    float*       out     = (float*)d_out;

    cudaFuncSetAttribute(gemm_c1,  cudaFuncAttributeMaxDynamicSharedMemorySize, SMEM_T);
    cudaFuncSetAttribute(gemm_mix, cudaFuncAttributeMaxDynamicSharedMemorySize, SMEM_T);

    setup_all<<<(N_NODES*FOUT/4 + 255)/256, 256>>>((const int*)ei, means, logvars,
                                                   weight, out);
    prep_and_count<<<PREPB + CNTB, FIN>>>(x, means, logp, ei);
    compute_offsets<<<(N_NODES + 255)/256, 256>>>();
    scatter_edges<<<(N_EDGES + 255)/256, 256>>>(ei);
    spmm_kernel<<<N_NODES, 128>>>();

    const int MT = (N_NODES + 127) / 128;   // 157
    gemm_c1 <<<dim3(MT, 2), 256, SMEM_T>>>();
    gemm_mix<<<dim3(MT, 2, KMIX), 256, SMEM_T>>>(bias, out);
}

// round 15
// speedup vs baseline: 1.6337x; 1.0588x over previous
#include <cuda_runtime.h>
#include <cuda_fp16.h>
#include <math.h>
#include <stdint.h>

#define N_NODES 20000
#define N_EDGES 320000
#define KMIX    5
#define FIN     256
#define FOUT    128
#define KO      (KMIX*FOUT)   /* 640 */
#define MASKW   (FIN/32)      /* 8 */
#define NPB     8             /* nodes per block in prep_x */
#define PREPB   (N_NODES/NPB) /* 2500 prep blocks */
#define CNTB    ((N_EDGES + 255)/256) /* 1250 count blocks */

// ---------------- static device scratch (no allocs allowed) ----------------
static __device__ __align__(16) half     g_X0h[N_NODES*FIN];
static __device__ __align__(16) unsigned g_mask[N_NODES*MASKW];
static __device__ __align__(16) float    g_gamma[KMIX*N_NODES];
static __device__ __align__(16) float    g_invvar[KMIX*FIN];
static __device__ __align__(16) float    g_dinv[N_NODES];
static __device__ __align__(16) int      g_cnt[N_NODES];
static __device__ __align__(16) int      g_rowptr[N_NODES+1];
static __device__ __align__(16) int      g_wpos[N_NODES];
static __device__ __align__(16) int      g_ccol[N_EDGES];
static __device__ __align__(16) float    g_swn[N_NODES];
static __device__ int g_total;
// fp16 A matrices (SpMM outputs), row-major [N_NODES, 256]
static __device__ __align__(16) half     g_G1[N_NODES*FIN];
static __device__ __align__(16) half     g_G2[N_NODES*FIN];
static __device__ __align__(16) half     g_G3[N_NODES*FIN];
// fp16 transposed weights: [NCOLS rows x 256 K] K-major (= B^T)
static __device__ __align__(16) half     g_Wt [FOUT*FIN];
static __device__ __align__(16) half     g_Wmt[KO*FIN];
static __device__ __align__(16) half     g_Wct[KO*FIN];
// fp16 c1 = G1 @ W
static __device__ __align__(16) half     g_C1[N_NODES*FOUT];
static __device__ int g_is64;

// ================= helpers =================================================
__device__ __forceinline__ uint32_t smem_u32(const void* p) {
    uint32_t a;
    asm("{ .reg .u64 t; cvta.to.shared.u64 t, %1; cvt.u32.u64 %0, t; }" : "=r"(a) : "l"(p));
    return a;
}
#define SW128(o) ((o) ^ (((o) >> 3) & 0x70))

__device__ __forceinline__ void ldsm_x4(uint32_t* r, uint32_t addr) {
    asm volatile("ldmatrix.sync.aligned.m8n8.x4.shared.b16 {%0,%1,%2,%3}, [%4];"
                 : "=r"(r[0]), "=r"(r[1]), "=r"(r[2]), "=r"(r[3]) : "r"(addr));
}
__device__ __forceinline__ void mma_fp16(float* c, const uint32_t* a,
                                         uint32_t b0, uint32_t b1) {
    asm volatile(
        "mma.sync.aligned.m16n8k16.row.col.f32.f16.f16.f32 "
        "{%0,%1,%2,%3},{%4,%5,%6,%7},{%8,%9},{%0,%1,%2,%3};"
        : "+f"(c[0]), "+f"(c[1]), "+f"(c[2]), "+f"(c[3])
        : "r"(a[0]), "r"(a[1]), "r"(a[2]), "r"(a[3]), "r"(b0), "r"(b1));
}
__device__ __forceinline__ void cp_async16(uint32_t dst, const void* src, bool valid) {
    int sz = valid ? 16 : 0;
    asm volatile("cp.async.cg.shared.global [%0], [%1], 16, %2;"
                 :: "r"(dst), "l"(src), "r"(sz));
}
#define CP_COMMIT() asm volatile("cp.async.commit_group;" ::: "memory")
#define CP_WAIT1()  asm volatile("cp.async.wait_group 1;" ::: "memory")
#define CP_WAIT0()  asm volatile("cp.async.wait_group 0;" ::: "memory")

__device__ __forceinline__ int load_row(const void* ei, int e) {
    if (g_is64) return (int)((const long long*)ei)[e];
    return ((const int*)ei)[e];
}
__device__ __forceinline__ int load_col(const void* ei, int e) {
    if (g_is64) return (int)((const long long*)ei)[N_EDGES + e];
    return ((const int*)ei)[N_EDGES + e];
}

// ---------------- merged setup: detect dtype + weights + cnt + zero out ----
__global__ void setup_all(const int* __restrict__ ei32,
                          const float* __restrict__ means,
                          const float* __restrict__ logvars,
                          const float* __restrict__ W,
                          float* __restrict__ out) {
    int idx = blockIdx.x * blockDim.x + threadIdx.x;
    if (idx == 0) {
        int is64 = 1;
        for (int i = 0; i < 128; i++)
            if (ei32[2*i + 1] != 0) { is64 = 0; break; }
        g_is64 = is64;
        g_total = 0;
    }
    if (idx < N_NODES) g_cnt[idx] = 0;
    if (idx < KMIX*FIN) g_invvar[idx] = expf(-logvars[idx]);
    if (idx < KO*FIN) {
        int j = idx / FIN, i = idx % FIN;               // j = k*FOUT+o
        int k = j / FOUT, o = j % FOUT;
        float w = W[i*FOUT + o];
        g_Wmt[idx] = __float2half_rn(means[k*FIN + i] * w);
        g_Wct[idx] = __float2half_rn(expf(logvars[k*FIN + i]) * w * w);
        if (j < FOUT) g_Wt[idx] = __float2half_rn(W[i*FOUT + j]);
    }
    if (idx < (N_NODES*FOUT)/4)
        ((float4*)out)[idx] = make_float4(0.f, 0.f, 0.f, 0.f);
}

// ---------------- fused prep_x (float2) + count_deg ------------------------
// Paired mask layout: for node n, word 2p holds isn bits of EVEN features
// 64p+2l (l = lane), word 2p+1 holds ODD features 64p+2l+1.
// Prep: half-block h handles node nbase+2*it+h; thread pair-index tt = t&127
// covers features (2tt, 2tt+1); warp group wp = tt>>5 = p.
__global__ __launch_bounds__(FIN) void prep_and_count(const float* __restrict__ x,
                       const float* __restrict__ means,
                       const float* __restrict__ logp,
                       const void* __restrict__ ei) {
    if (blockIdx.x >= PREPB) {
        int e = (blockIdx.x - PREPB) * 256 + threadIdx.x;
        if (e < N_EDGES) atomicAdd(&g_cnt[load_row(ei, e)], 1);
        return;
    }
    int t = threadIdx.x;
    int h = t >> 7;                 // 0,1 (node within pair)
    int tt = t & 127;               // feature-pair index
    int lane = t & 31;
    int wp = tt >> 5;               // pair group p (0..3)
    int wid = t >> 5;               // warp 0..7
    int nbase = blockIdx.x * NPB;

    float mk0[KMIX], mk1[KMIX], iv0[KMIX], iv1[KMIX];
#pragma unroll
    for (int k = 0; k < KMIX; k++) {
        mk0[k] = means[k*FIN + 2*tt];
        mk1[k] = means[k*FIN + 2*tt + 1];
        iv0[k] = g_invvar[k*FIN + 2*tt];
        iv1[k] = g_invvar[k*FIN + 2*tt + 1];
    }

    __shared__ float red[NPB][4][KMIX];
    __shared__ float lpv[KMIX];
    if (t < KMIX) lpv[t] = logp[t];

#pragma unroll
    for (int it = 0; it < 4; it++) {
        int n = nbase + 2*it + h;
        float2 v = *(const float2*)(x + (size_t)n*FIN + 2*tt);
        bool i0 = !(v.x == v.x), i1 = !(v.y == v.y);
        ((__half2*)g_X0h)[(size_t)n*(FIN/2) + tt] =
            __floats2half2_rn(i0 ? 0.f : v.x, i1 ? 0.f : v.y);
        unsigned b0 = __ballot_sync(0xffffffffu, i0);
        unsigned b1 = __ballot_sync(0xffffffffu, i1);
        if (lane == 0) {
            g_mask[n*MASKW + 2*wp]     = b0;
            g_mask[n*MASKW + 2*wp + 1] = b1;
        }
        float d[KMIX];
#pragma unroll
        for (int k = 0; k < KMIX; k++) {
            float f0 = i0 ? 0.f : (v.x - mk0[k]);
            float f1 = i1 ? 0.f : (v.y - mk1[k]);
            d[k] = f0*f0*iv0[k] + f1*f1*iv1[k];
        }
#pragma unroll
        for (int k = 0; k < KMIX; k++)
            for (int off = 16; off > 0; off >>= 1)
                d[k] += __shfl_down_sync(0xffffffffu, d[k], off);
        if (lane == 0)
            for (int k = 0; k < KMIX; k++) red[2*it + h][wp][k] = d[k];
    }
    (void)wid;
    __syncthreads();
    if (t < NPB) {
        int n = nbase + t;
        float s[KMIX], m = -1e30f;
#pragma unroll
        for (int k = 0; k < KMIX; k++) {
            float acc = 0.f;
            for (int ww = 0; ww < 4; ww++) acc += red[t][ww][k];
            s[k] = lpv[k] - 0.5f * acc;
            m = fmaxf(m, s[k]);
        }
        float ssum = 0.f, e[KMIX];
#pragma unroll
        for (int k = 0; k < KMIX; k++) { e[k] = expf(s[k] - m); ssum += e[k]; }
        float inv = 1.f / ssum;
#pragma unroll
        for (int k = 0; k < KMIX; k++) g_gamma[k*N_NODES + n] = e[k] * inv;
    }
}

// ---------------- CSR build ------------------------------------------------
__global__ __launch_bounds__(256) void compute_offsets() {
    __shared__ int wsums[8];
    __shared__ int blockbase;
    int i = blockIdx.x * 256 + threadIdx.x;
    int lane = threadIdx.x & 31, w = threadIdx.x >> 5;
    int v = (i < N_NODES) ? g_cnt[i] : 0;
    int xv = v;
#pragma unroll
    for (int off = 1; off < 32; off <<= 1) {
        int y = __shfl_up_sync(0xffffffffu, xv, off);
        if (lane >= off) xv += y;
    }
    if (lane == 31) wsums[w] = xv;
    __syncthreads();
    if (threadIdx.x == 0) {
        int s = 0;
#pragma unroll
        for (int j = 0; j < 8; j++) { int tv = wsums[j]; wsums[j] = s; s += tv; }
        blockbase = atomicAdd(&g_total, s);
    }
    __syncthreads();
    if (i < N_NODES) {
        int start = blockbase + wsums[w] + (xv - v);
        g_rowptr[i] = start;
        g_wpos[i]   = start;
        g_dinv[i]   = rsqrtf((float)(v + 1));
    }
}

// 2 far-strided edges per thread -> 2 independent atomic chains
__global__ void scatter_edges(const void* __restrict__ ei) {
    int tid0 = blockIdx.x * blockDim.x + threadIdx.x;  // 0..159999
#pragma unroll
    for (int hh = 0; hh < 2; hh++) {
        int e = tid0 + hh * (N_EDGES/2);
        int r = load_row(ei, e);
        int c = load_col(ei, e);
        int p = atomicAdd(&g_wpos[r], 1);
        g_ccol[p] = c;
    }
}

// ---------------- fused SpMM (fp16 gather, 8-edge unroll, paired mask) -----
__global__ __launch_bounds__(128) void spmm_kernel() {
    int r = blockIdx.x;
    int t = threadIdx.x;               // 0..127
    int p = t >> 5;                    // pair group
    int l = t & 31;
    float dr = g_dinv[r];
    int start = g_rowptr[r], end = start + g_cnt[r];
    float a1x=0.f, a1y=0.f, a2x=0.f, a2y=0.f, a3x=0.f, a3y=0.f, sw=0.f;
    const __half2* X = (const __half2*)g_X0h;

    int e = start;
    for (; e + 8 <= end; e += 8) {
        int   c[8]; float d[8]; float2 xv[8]; uint2 mm[8];
#pragma unroll
        for (int q = 0; q < 8; q++) c[q] = g_ccol[e + q];
#pragma unroll
        for (int q = 0; q < 8; q++) d[q] = g_dinv[c[q]];
#pragma unroll
        for (int q = 0; q < 8; q++) xv[q] = __half22float2(X[c[q]*(FIN/2) + t]);
#pragma unroll
        for (int q = 0; q < 8; q++) mm[q] = *(const uint2*)&g_mask[c[q]*MASKW + 2*p];
#pragma unroll
        for (int q = 0; q < 8; q++) {
            a1x += d[q]*xv[q].x; a1y += d[q]*xv[q].y;
            if ((mm[q].x >> l) & 1u) { a2x += d[q]; a3x += d[q]*d[q]; }
            if ((mm[q].y >> l) & 1u) { a2y += d[q]; a3y += d[q]*d[q]; }
            sw += d[q];
        }
    }
    for (; e < end; e++) {
        int c0 = g_ccol[e];
        float d0 = g_dinv[c0];
        float2 x0 = __half22float2(X[c0*(FIN/2) + t]);
        uint2 m0 = *(const uint2*)&g_mask[c0*MASKW + 2*p];
        a1x += d0*x0.x; a1y += d0*x0.y;
        if ((m0.x >> l) & 1u) { a2x += d0; a3x += d0*d0; }
        if ((m0.y >> l) & 1u) { a2y += d0; a3y += d0*d0; }
        sw += d0;
    }
    {   // self loop
        float2 xr = __half22float2(X[r*(FIN/2) + t]);
        uint2 mr = *(const uint2*)&g_mask[r*MASKW + 2*p];
        a1x += dr*xr.x; a1y += dr*xr.y;
        if ((mr.x >> l) & 1u) { a2x += dr; a3x += dr*dr; }
        if ((mr.y >> l) & 1u) { a2y += dr; a3y += dr*dr; }
        sw += dr;
    }
    size_t o = (size_t)r*(FIN/2) + t;
    float dr2 = dr * dr;
    ((__half2*)g_G1)[o] = __floats2half2_rn(dr * a1x,  dr * a1y);
    ((__half2*)g_G2)[o] = __floats2half2_rn(dr * a2x,  dr * a2y);
    ((__half2*)g_G3)[o] = __floats2half2_rn(dr2 * a3x, dr2 * a3y);
    if (t == 0) g_swn[r] = dr * sw;
}

// ---------------- fused GEMMs (fp16 single pass, frozen core) --------------
// CTA tile 128 rows x 64 cols; 8 warps (4M x 2N), warp tile 32x32.
#define STA 0
#define STB 16384
#define STG_SZ 24576
#define SMEM_T (2*STG_SZ)   /* 48 KB */

__device__ __forceinline__ float ex_relu(float mu, float sig) {
    if (sig <= 0.f) return fmaxf(mu, 0.f);
    float ss = sqrtf(sig);
    float w = mu / ss;
    return ss * (expf(-0.5f * w * w) * 0.3989422804014327f
                 + 0.5f * w * (1.f + erff(w * 0.7071067811865476f)));
}

__device__ __forceinline__ void compute_chunk(uint32_t base, uint32_t aRowOff,
                                              uint32_t bRowOff, uint32_t lhc,
                                              uint32_t swz, float (&acc)[2][4][4]) {
#pragma unroll
    for (int ks = 0; ks < 4; ks++) {
        uint32_t xoff = ((uint32_t)ks * 32 + lhc) ^ swz;
        uint32_t a[2][4], b[2][4];
        ldsm_x4(a[0], base + STA + aRowOff + xoff);
        ldsm_x4(a[1], base + STA + aRowOff + 16*128 + xoff);
        ldsm_x4(b[0], base + STB + bRowOff + xoff);
        ldsm_x4(b[1], base + STB + bRowOff + 16*128 + xoff);
#pragma unroll
        for (int mf = 0; mf < 2; mf++)
#pragma unroll
            for (int nf = 0; nf < 2; nf++) {
                mma_fp16(acc[mf][2*nf],   a[mf], b[nf][0], b[nf][2]);
                mma_fp16(acc[mf][2*nf+1], a[mf], b[nf][1], b[nf][3]);
            }
    }
}

// ---- phase 0: c1 = G1 @ W -> g_C1 (fp16), grid (157, 2) ----
__global__ __launch_bounds__(256, 2) void gemm_c1() {
    const int tile = blockIdx.x, nh = blockIdx.y;
    extern __shared__ __align__(1024) char smem[];
    uint32_t smb = smem_u32(smem);
    int tid = threadIdx.x;
    int wid = tid >> 5, lane = tid & 31;
    int wm = wid >> 1, wn = wid & 1;
    int lrow = lane & 15;
    uint32_t lhc = (uint32_t)(lane >> 4) * 16;
    uint32_t swz = (uint32_t)(lrow & 7) << 4;
    uint32_t aRowOff = (uint32_t)(wm * 32 + lrow) * 128;
    uint32_t bRowOff = (uint32_t)(wn * 32 + lrow) * 128;

    float acc[2][4][4];
#pragma unroll
    for (int i = 0; i < 2; i++)
#pragma unroll
        for (int j = 0; j < 4; j++)
#pragma unroll
            for (int q = 0; q < 4; q++) acc[i][j][q] = 0.f;

    auto load_stage = [&](int kc, int buf) {
        uint32_t base = smb + buf * STG_SZ;
#pragma unroll
        for (int it = 0; it < 4; it++) {
            int idx = it * 256 + tid;
            int row = idx >> 3, kq = idx & 7;
            uint32_t so = SW128((uint32_t)row * 128 + (uint32_t)kq * 16);
            int grow = tile * 128 + row;
            bool av = grow < N_NODES;
            size_t go = (size_t)(av ? grow : 0) * FIN + kc * 64 + kq * 8;
            cp_async16(base + STA + so, g_G1 + go, av);
        }
#pragma unroll
        for (int it = 0; it < 2; it++) {
            int idx = it * 256 + tid;
            int row = idx >> 3, kq = idx & 7;
            uint32_t so = SW128((uint32_t)row * 128 + (uint32_t)kq * 16);
            size_t bo = (size_t)(nh * 64 + row) * FIN + kc * 64 + kq * 8;
            cp_async16(base + STB + so, g_Wt + bo, true);
        }
        CP_COMMIT();
    };

    load_stage(0, 0);
    load_stage(1, 1);
    for (int ch = 0; ch < 4; ch++) {
        if (ch < 3) { CP_WAIT1(); } else { CP_WAIT0(); }
        __syncthreads();
        compute_chunk(smb + (ch & 1) * STG_SZ, aRowOff, bRowOff, lhc, swz, acc);
        __syncthreads();
        if (ch + 2 < 4) load_stage(ch + 2, ch & 1);
    }

    int cb = nh * 64 + wn * 32 + (lane & 3) * 2;
#pragma unroll
    for (int mf = 0; mf < 2; mf++) {
        int r0 = tile * 128 + wm * 32 + mf * 16 + (lane >> 2);
#pragma unroll
        for (int n8 = 0; n8 < 4; n8++) {
            int c = cb + n8 * 8;
            if (r0 < N_NODES)
                *(__half2*)(g_C1 + (size_t)r0 * FOUT + c) =
                    __floats2half2_rn(acc[mf][n8][0], acc[mf][n8][1]);
            if (r0 + 8 < N_NODES)
                *(__half2*)(g_C1 + (size_t)(r0 + 8) * FOUT + c) =
                    __floats2half2_rn(acc[mf][n8][2], acc[mf][n8][3]);
        }
    }
}

// ---- phase 1: mx/cv GEMMs + fused ExRelu epilogue, grid (157, 2, 5) ----
__global__ __launch_bounds__(256, 2) void gemm_mix(const float* __restrict__ bias,
                                                   float* __restrict__ out) {
    const int tile = blockIdx.x, nh = blockIdx.y, kk = blockIdx.z;

    extern __shared__ __align__(1024) char smem[];
    uint32_t smb = smem_u32(smem);
    int tid = threadIdx.x;
    int wid = tid >> 5, lane = tid & 31;
    int wm = wid >> 1, wn = wid & 1;
    int lrow = lane & 15;
    uint32_t lhc = (uint32_t)(lane >> 4) * 16;
    uint32_t swz = (uint32_t)(lrow & 7) << 4;
    uint32_t aRowOff = (uint32_t)(wm * 32 + lrow) * 128;
    uint32_t bRowOff = (uint32_t)(wn * 32 + lrow) * 128;

    float mxr[2][4][4], acc[2][4][4];
#pragma unroll
    for (int i = 0; i < 2; i++)
#pragma unroll
        for (int j = 0; j < 4; j++)
#pragma unroll
            for (int q = 0; q < 4; q++) { mxr[i][j][q] = 0.f; acc[i][j][q] = 0.f; }

    auto load_stage = [&](int ch, int buf) {
        int phase = ch >> 2;
        int kc = ch & 3;
        const half* __restrict__ A = phase ? g_G3 : g_G2;
        const half* __restrict__ B = phase ? g_Wct : g_Wmt;
        int jb0 = kk * FOUT + nh * 64;
        uint32_t base = smb + buf * STG_SZ;
#pragma unroll
        for (int it = 0; it < 4; it++) {
            int idx = it * 256 + tid;
            int row = idx >> 3, kq = idx & 7;
            uint32_t so = SW128((uint32_t)row * 128 + (uint32_t)kq * 16);
            int grow = tile * 128 + row;
            bool av = grow < N_NODES;
            size_t go = (size_t)(av ? grow : 0) * FIN + kc * 64 + kq * 8;
            cp_async16(base + STA + so, A + go, av);
        }
#pragma unroll
        for (int it = 0; it < 2; it++) {
            int idx = it * 256 + tid;
            int row = idx >> 3, kq = idx & 7;
            uint32_t so = SW128((uint32_t)row * 128 + (uint32_t)kq * 16);
            size_t bo = (size_t)(jb0 + row) * FIN + kc * 64 + kq * 8;
            cp_async16(base + STB + so, B + bo, true);
        }
        CP_COMMIT();
    };

    load_stage(0, 0);
    load_stage(1, 1);
    for (int ch = 0; ch < 8; ch++) {
        if (ch < 7) { CP_WAIT1(); } else { CP_WAIT0(); }
        __syncthreads();
        uint32_t base = smb + (ch & 1) * STG_SZ;
        if (ch < 4)
            compute_chunk(base, aRowOff, bRowOff, lhc, swz, mxr);
        else
            compute_chunk(base, aRowOff, bRowOff, lhc, swz, acc);
        __syncthreads();
        if (ch + 2 < 8) load_stage(ch + 2, ch & 1);
    }

    // epilogue: out += gamma_k * exrelu(c1 + mx + swn*bias, cv)
    int cb = nh * 64 + wn * 32 + (lane & 3) * 2;
#pragma unroll
    for (int mf = 0; mf < 2; mf++) {
#pragma unroll
        for (int rh = 0; rh < 2; rh++) {
            int r = tile * 128 + wm * 32 + mf * 16 + (lane >> 2) + rh * 8;
            if (r >= N_NODES) continue;
            float ga = g_gamma[kk * N_NODES + r];
            float swr = g_swn[r];
#pragma unroll
            for (int n8 = 0; n8 < 4; n8++) {
                int c = cb + n8 * 8;
                float2 c1v = __half22float2(*(const __half2*)(g_C1 + (size_t)r * FOUT + c));
                float2 bv  = *(const float2*)(bias + c);
                float mu0 = c1v.x + mxr[mf][n8][2*rh]   + swr * bv.x;
                float mu1 = c1v.y + mxr[mf][n8][2*rh+1] + swr * bv.y;
                float t0 = ga * ex_relu(mu0, acc[mf][n8][2*rh]);
                float t1 = ga * ex_relu(mu1, acc[mf][n8][2*rh+1]);
                atomicAdd(out + (size_t)r * FOUT + c,     t0);
                atomicAdd(out + (size_t)r * FOUT + c + 1, t1);
            }
        }
    }
}

// ---------------- launch ---------------------------------------------------
extern "C" void kernel_launch(void* const* d_in, const int* in_sizes, int n_in,
                              void* d_out, int out_size) {
    const float* x       = (const float*)d_in[0];
    const void*  ei      = d_in[1];
    const float* logp    = (const float*)d_in[2];
    const float* means   = (const float*)d_in[3];
    const float* logvars = (const float*)d_in[4];
    const float* weight  = (const float*)d_in[5];
    const float* bias    = (const float*)d_in[6];
    float*       out     = (float*)d_out;

    cudaFuncSetAttribute(gemm_c1,  cudaFuncAttributeMaxDynamicSharedMemorySize, SMEM_T);
    cudaFuncSetAttribute(gemm_mix, cudaFuncAttributeMaxDynamicSharedMemorySize, SMEM_T);

    setup_all<<<(N_NODES*FOUT/4 + 255)/256, 256>>>((const int*)ei, means, logvars,
                                                   weight, out);
    prep_and_count<<<PREPB + CNTB, FIN>>>(x, means, logp, ei);
    compute_offsets<<<(N_NODES + 255)/256, 256>>>();
    scatter_edges<<<(N_EDGES/2 + 255)/256, 256>>>(ei);
    spmm_kernel<<<N_NODES, 128>>>();

    const int MT = (N_NODES + 127) / 128;   // 157
    gemm_c1 <<<dim3(MT, 2), 256, SMEM_T>>>();
    gemm_mix<<<dim3(MT, 2, KMIX), 256, SMEM_T>>>(bias, out);
}

// round 16
// speedup vs baseline: 1.6727x; 1.0238x over previous
#include <cuda_runtime.h>
#include <cuda_fp16.h>
#include <math.h>
#include <stdint.h>

#define N_NODES 20000
#define N_EDGES 320000
#define KMIX    5
#define FIN     256
#define FOUT    128
#define KO      (KMIX*FOUT)   /* 640 */
#define MASKW   (FIN/32)      /* 8 */
#define NPB     8             /* nodes per block in prep_x */
#define PREPB   (N_NODES/NPB) /* 2500 prep blocks */
#define CNTB    ((N_EDGES + 255)/256) /* 1250 count blocks */
#define NTILES  157           /* M tiles of 128 rows */
#define NPADR   (NTILES*128)  /* 20096 padded rows */

// ---------------- static device scratch (no allocs allowed) ----------------
static __device__ __align__(16) half     g_X0h[N_NODES*FIN];
static __device__ __align__(16) unsigned g_mask[N_NODES*MASKW];
static __device__ __align__(16) float    g_gamma[KMIX*N_NODES];
static __device__ __align__(16) float    g_invvar[KMIX*FIN];
static __device__ __align__(16) float    g_dinv[N_NODES];
static __device__ __align__(16) int      g_cnt[N_NODES];
static __device__ __align__(16) int      g_rowptr[N_NODES+1];
static __device__ __align__(16) int      g_wpos[N_NODES];
static __device__ __align__(16) int      g_ccol[N_EDGES];
static __device__ __align__(16) float    g_swn[N_NODES];
static __device__ int g_total;
// fp16 A matrices: chunk-major pre-swizzled [kc][tile][16KB image], padded
static __device__ __align__(16) half     g_G1[(size_t)NPADR*FIN];
static __device__ __align__(16) half     g_G2[(size_t)NPADR*FIN];
static __device__ __align__(16) half     g_G3[(size_t)NPADR*FIN];
// fp16 weights: B-tile-major pre-swizzled [(col_block*4+kc)][8KB image]
static __device__ __align__(16) half     g_Wt [FOUT*FIN];
static __device__ __align__(16) half     g_Wmt[KO*FIN];
static __device__ __align__(16) half     g_Wct[KO*FIN];
// fp16 c1 = G1 @ W (row-major)
static __device__ __align__(16) half     g_C1[N_NODES*FOUT];
static __device__ int g_is64;

// ================= helpers =================================================
__device__ __forceinline__ uint32_t smem_u32(const void* p) {
    uint32_t a;
    asm("{ .reg .u64 t; cvta.to.shared.u64 t, %1; cvt.u32.u64 %0, t; }" : "=r"(a) : "l"(p));
    return a;
}
#define SW128(o) ((o) ^ (((o) >> 3) & 0x70))

__device__ __forceinline__ void ldsm_x4(uint32_t* r, uint32_t addr) {
    asm volatile("ldmatrix.sync.aligned.m8n8.x4.shared.b16 {%0,%1,%2,%3}, [%4];"
                 : "=r"(r[0]), "=r"(r[1]), "=r"(r[2]), "=r"(r[3]) : "r"(addr));
}
__device__ __forceinline__ void mma_fp16(float* c, const uint32_t* a,
                                         uint32_t b0, uint32_t b1) {
    asm volatile(
        "mma.sync.aligned.m16n8k16.row.col.f32.f16.f16.f32 "
        "{%0,%1,%2,%3},{%4,%5,%6,%7},{%8,%9},{%0,%1,%2,%3};"
        : "+f"(c[0]), "+f"(c[1]), "+f"(c[2]), "+f"(c[3])
        : "r"(a[0]), "r"(a[1]), "r"(a[2]), "r"(a[3]), "r"(b0), "r"(b1));
}
// bulk async copy global->shared with mbarrier completion
__device__ __forceinline__ void bulk_g2s(uint32_t dst, const void* src,
                                         uint32_t bytes, uint32_t mbar) {
    asm volatile(
        "cp.async.bulk.shared::cta.global.mbarrier::complete_tx::bytes [%0], [%1], %2, [%3];"
        :: "r"(dst), "l"(src), "r"(bytes), "r"(mbar) : "memory");
}
#define MBAR_INIT(mb, c) asm volatile("mbarrier.init.shared.b64 [%0], %1;" :: "r"(mb), "r"((uint32_t)(c)) : "memory")
#define MBAR_EXPTX(mb, n) asm volatile("mbarrier.arrive.expect_tx.shared.b64 _, [%0], %1;" :: "r"(mb), "r"((uint32_t)(n)) : "memory")
__device__ __forceinline__ void mbar_wait(uint32_t mb, uint32_t parity) {
    asm volatile(
        "{\n\t.reg .pred P1;\n\t"
        "WAIT_LOOP_%=:\n\t"
        "mbarrier.try_wait.parity.acquire.cta.shared::cta.b64 P1, [%0], %1, 0x989680;\n\t"
        "@P1 bra.uni WAIT_DONE_%=;\n\t"
        "bra.uni WAIT_LOOP_%=;\n\t"
        "WAIT_DONE_%=:\n\t}"
        :: "r"(mb), "r"(parity) : "memory");
}

__device__ __forceinline__ int load_row(const void* ei, int e) {
    if (g_is64) return (int)((const long long*)ei)[e];
    return ((const int*)ei)[e];
}
__device__ __forceinline__ int load_col(const void* ei, int e) {
    if (g_is64) return (int)((const long long*)ei)[N_EDGES + e];
    return ((const int*)ei)[N_EDGES + e];
}

// ---------------- merged setup: dtype + weights(swizzled) + cnt + zero -----
__global__ void setup_all(const int* __restrict__ ei32,
                          const float* __restrict__ means,
                          const float* __restrict__ logvars,
                          const float* __restrict__ W,
                          float* __restrict__ out) {
    int idx = blockIdx.x * blockDim.x + threadIdx.x;
    if (idx == 0) {
        int is64 = 1;
        for (int i = 0; i < 128; i++)
            if (ei32[2*i + 1] != 0) { is64 = 0; break; }
        g_is64 = is64;
        g_total = 0;
    }
    if (idx < N_NODES) g_cnt[idx] = 0;
    if (idx < KMIX*FIN) g_invvar[idx] = expf(-logvars[idx]);
    if (idx < KO*FIN) {
        int j = idx / FIN, i = idx % FIN;               // j = col (k*FOUT+o), i = K
        int k = j / FOUT, o = j % FOUT;
        // B-tile swizzled address
        int cb = j >> 6, cl = j & 63, kc = i >> 6, il = i & 63;
        size_t boff = ((size_t)(cb*4 + kc)) * 8192
                    + SW128((uint32_t)(cl*128 + (il >> 3)*16)) + (il & 7)*2;
        float w = W[i*FOUT + o];
        *(half*)((char*)g_Wmt + boff) = __float2half_rn(means[k*FIN + i] * w);
        *(half*)((char*)g_Wct + boff) = __float2half_rn(expf(logvars[k*FIN + i]) * w * w);
        if (j < FOUT) {
            size_t toff = ((size_t)(cb*4 + kc)) * 8192
                        + SW128((uint32_t)(cl*128 + (il >> 3)*16)) + (il & 7)*2;
            *(half*)((char*)g_Wt + toff) = __float2half_rn(W[i*FOUT + j]);
        }
    }
    if (idx < (N_NODES*FOUT)/4)
        ((float4*)out)[idx] = make_float4(0.f, 0.f, 0.f, 0.f);
}

// ---------------- fused prep_x (float2) + count_deg ------------------------
// Paired mask layout: word 2p = even-feature bits, 2p+1 = odd-feature bits.
__global__ __launch_bounds__(FIN) void prep_and_count(const float* __restrict__ x,
                       const float* __restrict__ means,
                       const float* __restrict__ logp,
                       const void* __restrict__ ei) {
    if (blockIdx.x >= PREPB) {
        int e = (blockIdx.x - PREPB) * 256 + threadIdx.x;
        if (e < N_EDGES) atomicAdd(&g_cnt[load_row(ei, e)], 1);
        return;
    }
    int t = threadIdx.x;
    int h = t >> 7;
    int tt = t & 127;
    int lane = t & 31;
    int wp = tt >> 5;
    int nbase = blockIdx.x * NPB;

    float mk0[KMIX], mk1[KMIX], iv0[KMIX], iv1[KMIX];
#pragma unroll
    for (int k = 0; k < KMIX; k++) {
        mk0[k] = means[k*FIN + 2*tt];
        mk1[k] = means[k*FIN + 2*tt + 1];
        iv0[k] = g_invvar[k*FIN + 2*tt];
        iv1[k] = g_invvar[k*FIN + 2*tt + 1];
    }

    __shared__ float red[NPB][4][KMIX];
    __shared__ float lpv[KMIX];
    if (t < KMIX) lpv[t] = logp[t];

#pragma unroll
    for (int it = 0; it < 4; it++) {
        int n = nbase + 2*it + h;
        float2 v = *(const float2*)(x + (size_t)n*FIN + 2*tt);
        bool i0 = !(v.x == v.x), i1 = !(v.y == v.y);
        ((__half2*)g_X0h)[(size_t)n*(FIN/2) + tt] =
            __floats2half2_rn(i0 ? 0.f : v.x, i1 ? 0.f : v.y);
        unsigned b0 = __ballot_sync(0xffffffffu, i0);
        unsigned b1 = __ballot_sync(0xffffffffu, i1);
        if (lane == 0) {
            g_mask[n*MASKW + 2*wp]     = b0;
            g_mask[n*MASKW + 2*wp + 1] = b1;
        }
        float d[KMIX];
#pragma unroll
        for (int k = 0; k < KMIX; k++) {
            float f0 = i0 ? 0.f : (v.x - mk0[k]);
            float f1 = i1 ? 0.f : (v.y - mk1[k]);
            d[k] = f0*f0*iv0[k] + f1*f1*iv1[k];
        }
#pragma unroll
        for (int k = 0; k < KMIX; k++)
            for (int off = 16; off > 0; off >>= 1)
                d[k] += __shfl_down_sync(0xffffffffu, d[k], off);
        if (lane == 0)
            for (int k = 0; k < KMIX; k++) red[2*it + h][wp][k] = d[k];
    }
    __syncthreads();
    if (t < NPB) {
        int n = nbase + t;
        float s[KMIX], m = -1e30f;
#pragma unroll
        for (int k = 0; k < KMIX; k++) {
            float acc = 0.f;
            for (int ww = 0; ww < 4; ww++) acc += red[t][ww][k];
            s[k] = lpv[k] - 0.5f * acc;
            m = fmaxf(m, s[k]);
        }
        float ssum = 0.f, e[KMIX];
#pragma unroll
        for (int k = 0; k < KMIX; k++) { e[k] = expf(s[k] - m); ssum += e[k]; }
        float inv = 1.f / ssum;
#pragma unroll
        for (int k = 0; k < KMIX; k++) g_gamma[k*N_NODES + n] = e[k] * inv;
    }
}

// ---------------- CSR build ------------------------------------------------
__global__ __launch_bounds__(256) void compute_offsets() {
    __shared__ int wsums[8];
    __shared__ int blockbase;
    int i = blockIdx.x * 256 + threadIdx.x;
    int lane = threadIdx.x & 31, w = threadIdx.x >> 5;
    int v = (i < N_NODES) ? g_cnt[i] : 0;
    int xv = v;
#pragma unroll
    for (int off = 1; off < 32; off <<= 1) {
        int y = __shfl_up_sync(0xffffffffu, xv, off);
        if (lane >= off) xv += y;
    }
    if (lane == 31) wsums[w] = xv;
    __syncthreads();
    if (threadIdx.x == 0) {
        int s = 0;
#pragma unroll
        for (int j = 0; j < 8; j++) { int tv = wsums[j]; wsums[j] = s; s += tv; }
        blockbase = atomicAdd(&g_total, s);
    }
    __syncthreads();
    if (i < N_NODES) {
        int start = blockbase + wsums[w] + (xv - v);
        g_rowptr[i] = start;
        g_wpos[i]   = start;
        g_dinv[i]   = rsqrtf((float)(v + 1));
    }
}

__global__ void scatter_edges(const void* __restrict__ ei) {
    int tid0 = blockIdx.x * blockDim.x + threadIdx.x;
#pragma unroll
    for (int hh = 0; hh < 2; hh++) {
        int e = tid0 + hh * (N_EDGES/2);
        int r = load_row(ei, e);
        int c = load_col(ei, e);
        int p = atomicAdd(&g_wpos[r], 1);
        g_ccol[p] = c;
    }
}

// ---------------- fused SpMM -> chunk-major swizzled G1/G2/G3 --------------
__global__ __launch_bounds__(128) void spmm_kernel() {
    int r = blockIdx.x;
    int t = threadIdx.x;               // 0..127
    int p = t >> 5;                    // pair group (for mask)
    int l = t & 31;
    float dr = g_dinv[r];
    int start = g_rowptr[r], end = start + g_cnt[r];
    float a1x=0.f, a1y=0.f, a2x=0.f, a2y=0.f, a3x=0.f, a3y=0.f, sw=0.f;
    const __half2* X = (const __half2*)g_X0h;

    int e = start;
    for (; e + 8 <= end; e += 8) {
        int   c[8]; float d[8]; float2 xv[8]; uint2 mm[8];
#pragma unroll
        for (int q = 0; q < 8; q++) c[q] = g_ccol[e + q];
#pragma unroll
        for (int q = 0; q < 8; q++) d[q] = g_dinv[c[q]];
#pragma unroll
        for (int q = 0; q < 8; q++) xv[q] = __half22float2(X[c[q]*(FIN/2) + t]);
#pragma unroll
        for (int q = 0; q < 8; q++) mm[q] = *(const uint2*)&g_mask[c[q]*MASKW + 2*p];
#pragma unroll
        for (int q = 0; q < 8; q++) {
            a1x += d[q]*xv[q].x; a1y += d[q]*xv[q].y;
            if ((mm[q].x >> l) & 1u) { a2x += d[q]; a3x += d[q]*d[q]; }
            if ((mm[q].y >> l) & 1u) { a2y += d[q]; a3y += d[q]*d[q]; }
            sw += d[q];
        }
    }
    for (; e < end; e++) {
        int c0 = g_ccol[e];
        float d0 = g_dinv[c0];
        float2 x0 = __half22float2(X[c0*(FIN/2) + t]);
        uint2 m0 = *(const uint2*)&g_mask[c0*MASKW + 2*p];
        a1x += d0*x0.x; a1y += d0*x0.y;
        if ((m0.x >> l) & 1u) { a2x += d0; a3x += d0*d0; }
        if ((m0.y >> l) & 1u) { a2y += d0; a3y += d0*d0; }
        sw += d0;
    }
    {   // self loop
        float2 xr = __half22float2(X[r*(FIN/2) + t]);
        uint2 mr = *(const uint2*)&g_mask[r*MASKW + 2*p];
        a1x += dr*xr.x; a1y += dr*xr.y;
        if ((mr.x >> l) & 1u) { a2x += dr; a3x += dr*dr; }
        if ((mr.y >> l) & 1u) { a2y += dr; a3y += dr*dr; }
        sw += dr;
    }
    // chunk-major swizzled write: tile image identical to smem stage image
    int tile = r >> 7, rloc = r & 127;
    int kc = t >> 5, pp = t & 31;
    size_t off = ((size_t)kc * NTILES + tile) * 16384
               + SW128((uint32_t)(rloc*128 + (pp >> 2)*16)) + (pp & 3)*4;
    float dr2 = dr * dr;
    *(__half2*)((char*)g_G1 + off) = __floats2half2_rn(dr * a1x,  dr * a1y);
    *(__half2*)((char*)g_G2 + off) = __floats2half2_rn(dr * a2x,  dr * a2y);
    *(__half2*)((char*)g_G3 + off) = __floats2half2_rn(dr2 * a3x, dr2 * a3y);
    if (t == 0) g_swn[r] = dr * sw;
}

// ---------------- fused GEMMs (fp16, bulk-copy loader) ---------------------
// CTA tile 128 rows x 64 cols; 8 warps (4M x 2N), warp tile 32x32. 2 stages.
#define STA 0
#define STB 16384
#define STG_SZ 24576
#define MB_OFF 49152
#define SMEM_T (49152 + 32)

__device__ __forceinline__ float ex_relu(float mu, float sig) {
    if (sig <= 0.f) return fmaxf(mu, 0.f);
    float ss = sqrtf(sig);
    float w = mu / ss;
    return ss * (expf(-0.5f * w * w) * 0.3989422804014327f
                 + 0.5f * w * (1.f + erff(w * 0.7071067811865476f)));
}

__device__ __forceinline__ void compute_chunk(uint32_t base, uint32_t aRowOff,
                                              uint32_t bRowOff, uint32_t lhc,
                                              uint32_t swz, float (&acc)[2][4][4]) {
#pragma unroll
    for (int ks = 0; ks < 4; ks++) {
        uint32_t xoff = ((uint32_t)ks * 32 + lhc) ^ swz;
        uint32_t a[2][4], b[2][4];
        ldsm_x4(a[0], base + STA + aRowOff + xoff);
        ldsm_x4(a[1], base + STA + aRowOff + 16*128 + xoff);
        ldsm_x4(b[0], base + STB + bRowOff + xoff);
        ldsm_x4(b[1], base + STB + bRowOff + 16*128 + xoff);
#pragma unroll
        for (int mf = 0; mf < 2; mf++)
#pragma unroll
            for (int nf = 0; nf < 2; nf++) {
                mma_fp16(acc[mf][2*nf],   a[mf], b[nf][0], b[nf][2]);
                mma_fp16(acc[mf][2*nf+1], a[mf], b[nf][1], b[nf][3]);
            }
    }
}

// ---- phase 0: c1 = G1 @ W -> g_C1 (fp16), grid (157, 2) ----
__global__ __launch_bounds__(256, 2) void gemm_c1() {
    const int tile = blockIdx.x, nh = blockIdx.y;
    extern __shared__ __align__(1024) char smem[];
    uint32_t smb = smem_u32(smem);
    int tid = threadIdx.x;
    int wid = tid >> 5, lane = tid & 31;
    int wm = wid >> 1, wn = wid & 1;
    int lrow = lane & 15;
    uint32_t lhc = (uint32_t)(lane >> 4) * 16;
    uint32_t swz = (uint32_t)(lrow & 7) << 4;
    uint32_t aRowOff = (uint32_t)(wm * 32 + lrow) * 128;
    uint32_t bRowOff = (uint32_t)(wn * 32 + lrow) * 128;

    float acc[2][4][4];
#pragma unroll
    for (int i = 0; i < 2; i++)
#pragma unroll
        for (int j = 0; j < 4; j++)
#pragma unroll
            for (int q = 0; q < 4; q++) acc[i][j][q] = 0.f;

    if (tid == 0) { MBAR_INIT(smb + MB_OFF, 1); MBAR_INIT(smb + MB_OFF + 8, 1); }
    __syncthreads();

    auto load_stage = [&](int kc, int buf) {
        if (tid == 0) {
            uint32_t mb = smb + MB_OFF + buf * 8;
            MBAR_EXPTX(mb, 24576);
            bulk_g2s(smb + buf*STG_SZ + STA,
                     (const char*)g_G1 + ((size_t)kc*NTILES + tile)*16384, 16384, mb);
            bulk_g2s(smb + buf*STG_SZ + STB,
                     (const char*)g_Wt + ((size_t)(nh*4 + kc))*8192, 8192, mb);
        }
    };

    load_stage(0, 0);
    load_stage(1, 1);
    for (int ch = 0; ch < 4; ch++) {
        mbar_wait(smb + MB_OFF + (ch & 1)*8, (ch >> 1) & 1);
        compute_chunk(smb + (ch & 1) * STG_SZ, aRowOff, bRowOff, lhc, swz, acc);
        __syncthreads();
        if (ch + 2 < 4) load_stage(ch + 2, ch & 1);
    }

    int cb = nh * 64 + wn * 32 + (lane & 3) * 2;
#pragma unroll
    for (int mf = 0; mf < 2; mf++) {
        int r0 = tile * 128 + wm * 32 + mf * 16 + (lane >> 2);
#pragma unroll
        for (int n8 = 0; n8 < 4; n8++) {
            int c = cb + n8 * 8;
            if (r0 < N_NODES)
                *(__half2*)(g_C1 + (size_t)r0 * FOUT + c) =
                    __floats2half2_rn(acc[mf][n8][0], acc[mf][n8][1]);
            if (r0 + 8 < N_NODES)
                *(__half2*)(g_C1 + (size_t)(r0 + 8) * FOUT + c) =
                    __floats2half2_rn(acc[mf][n8][2], acc[mf][n8][3]);
        }
    }
}

// ---- phase 1: mx/cv GEMMs + fused ExRelu epilogue, grid (157, 2, 5) ----
__global__ __launch_bounds__(256, 2) void gemm_mix(const float* __restrict__ bias,
                                                   float* __restrict__ out) {
    const int tile = blockIdx.x, nh = blockIdx.y, kk = blockIdx.z;

    extern __shared__ __align__(1024) char smem[];
    uint32_t smb = smem_u32(smem);
    int tid = threadIdx.x;
    int wid = tid >> 5, lane = tid & 31;
    int wm = wid >> 1, wn = wid & 1;
    int lrow = lane & 15;
    uint32_t lhc = (uint32_t)(lane >> 4) * 16;
    uint32_t swz = (uint32_t)(lrow & 7) << 4;
    uint32_t aRowOff = (uint32_t)(wm * 32 + lrow) * 128;
    uint32_t bRowOff = (uint32_t)(wn * 32 + lrow) * 128;
    const int colblk = kk * 2 + nh;    // B column-block index

    float mxr[2][4][4], acc[2][4][4];
#pragma unroll
    for (int i = 0; i < 2; i++)
#pragma unroll
        for (int j = 0; j < 4; j++)
#pragma unroll
            for (int q = 0; q < 4; q++) { mxr[i][j][q] = 0.f; acc[i][j][q] = 0.f; }

    if (tid == 0) { MBAR_INIT(smb + MB_OFF, 1); MBAR_INIT(smb + MB_OFF + 8, 1); }
    __syncthreads();

    auto load_stage = [&](int ch, int buf) {
        if (tid == 0) {
            int phase = ch >> 2;
            int kc = ch & 3;
            const char* A = (const char*)(phase ? g_G3 : g_G2);
            const char* B = (const char*)(phase ? g_Wct : g_Wmt);
            uint32_t mb = smb + MB_OFF + buf * 8;
            MBAR_EXPTX(mb, 24576);
            bulk_g2s(smb + buf*STG_SZ + STA,
                     A + ((size_t)kc*NTILES + tile)*16384, 16384, mb);
            bulk_g2s(smb + buf*STG_SZ + STB,
                     B + ((size_t)(colblk*4 + kc))*8192, 8192, mb);
        }
    };

    load_stage(0, 0);
    load_stage(1, 1);
    for (int ch = 0; ch < 8; ch++) {
        mbar_wait(smb + MB_OFF + (ch & 1)*8, (ch >> 1) & 1);
        uint32_t base = smb + (ch & 1) * STG_SZ;
        if (ch < 4)
            compute_chunk(base, aRowOff, bRowOff, lhc, swz, mxr);
        else
            compute_chunk(base, aRowOff, bRowOff, lhc, swz, acc);
        __syncthreads();
        if (ch + 2 < 8) load_stage(ch + 2, ch & 1);
    }

    // epilogue: out += gamma_k * exrelu(c1 + mx + swn*bias, cv)
    int cb = nh * 64 + wn * 32 + (lane & 3) * 2;
#pragma unroll
    for (int mf = 0; mf < 2; mf++) {
#pragma unroll
        for (int rh = 0; rh < 2; rh++) {
            int r = tile * 128 + wm * 32 + mf * 16 + (lane >> 2) + rh * 8;
            if (r >= N_NODES) continue;
            float ga = g_gamma[kk * N_NODES + r];
            float swr = g_swn[r];
#pragma unroll
            for (int n8 = 0; n8 < 4; n8++) {
                int c = cb + n8 * 8;
                float2 c1v = __half22float2(*(const __half2*)(g_C1 + (size_t)r * FOUT + c));
                float2 bv  = *(const float2*)(bias + c);
                float mu0 = c1v.x + mxr[mf][n8][2*rh]   + swr * bv.x;
                float mu1 = c1v.y + mxr[mf][n8][2*rh+1] + swr * bv.y;
                float t0 = ga * ex_relu(mu0, acc[mf][n8][2*rh]);
                float t1 = ga * ex_relu(mu1, acc[mf][n8][2*rh+1]);
                atomicAdd(out + (size_t)r * FOUT + c,     t0);
                atomicAdd(out + (size_t)r * FOUT + c + 1, t1);
            }
        }
    }
}

// ---------------- launch ---------------------------------------------------
extern "C" void kernel_launch(void* const* d_in, const int* in_sizes, int n_in,
                              void* d_out, int out_size) {
    const float* x       = (const float*)d_in[0];
    const void*  ei      = d_in[1];
    const float* logp    = (const float*)d_in[2];
    const float* means   = (const float*)d_in[3];
    const float* logvars = (const float*)d_in[4];
    const float* weight  = (const float*)d_in[5];
    const float* bias    = (const float*)d_in[6];
    float*       out     = (float*)d_out;

    cudaFuncSetAttribute(gemm_c1,  cudaFuncAttributeMaxDynamicSharedMemorySize, SMEM_T);
    cudaFuncSetAttribute(gemm_mix, cudaFuncAttributeMaxDynamicSharedMemorySize, SMEM_T);

    setup_all<<<(N_NODES*FOUT/4 + 255)/256, 256>>>((const int*)ei, means, logvars,
                                                   weight, out);
    prep_and_count<<<PREPB + CNTB, FIN>>>(x, means, logp, ei);
    compute_offsets<<<(N_NODES + 255)/256, 256>>>();
    scatter_edges<<<(N_EDGES/2 + 255)/256, 256>>>(ei);
    spmm_kernel<<<N_NODES, 128>>>();

    gemm_c1 <<<dim3(NTILES, 2), 256, SMEM_T>>>();
    gemm_mix<<<dim3(NTILES, 2, KMIX), 256, SMEM_T>>>(bias, out);
}